// round 9
// baseline (speedup 1.0000x reference)
#include <cuda_runtime.h>
#include <cuda_bf16.h>
#include <cstdint>
#include <cstdio>

// Mamba (8 layers) forward: B=2, L=2048, D=768, E=1536, N=16, Kconv=4, DTR=48
#define B_   2
#define L_   2048
#define D_   768
#define E_   1536
#define N_   16
#define KC   4
#define DTR_ 48
#define NL_  8
#define T_   (B_*L_)        // 4096 tokens
#define G_   (DTR_ + 2*N_)  // 80
#define EPSN 1e-5f
#define NCH  16             // scan chunks
#define CHL  (L_/NCH)       // 128 chunk length
#define BEN  (B_*E_*N_)     // 49152

typedef __nv_bfloat16 bf16;

// ---------------- scratch (static device globals; no allocation) ----------------
__device__ float g_h[(size_t)T_ * D_];          // residual stream (fp32)
__device__ bf16  g_hn[(size_t)T_ * D_];         // rmsnormed (bf16 for GEMM A)
__device__ float g_proj[(size_t)T_ * 2 * E_];   // in_proj out (u_pre | gate)
__device__ float g_u[(size_t)T_ * E_];          // conv+silu out
__device__ float g_ssm[(size_t)T_ * G_];        // x_proj out (dt_r | B | C)
__device__ float g_dt[(size_t)T_ * E_];         // softplus dt
__device__ bf16  g_y[(size_t)T_ * E_];          // scan out * silu(gate) (bf16)
__device__ float g_cP[(size_t)NCH * BEN];       // per-chunk decay product
__device__ float g_cS[(size_t)NCH * BEN];       // per-chunk local state
__device__ float g_cI[(size_t)NCH * BEN];       // per-chunk initial state
__device__ bf16  g_win_bf[(size_t)NL_ * 2 * E_ * D_];   // bf16 in_proj weights
__device__ bf16  g_wout_bf[(size_t)NL_ * D_ * E_];      // bf16 out_proj weights

__device__ __forceinline__ uint32_t s2u(const void* p) {
    return (uint32_t)__cvta_generic_to_shared(p);
}

// ---------------- fp32 -> bf16 weight conversion (grid-stride, x4) -------------
__global__ void f2bf_kernel(const float* __restrict__ in, bf16* __restrict__ out,
                            int nelem4) {
    int i = blockIdx.x * blockDim.x + threadIdx.x;
    if (i >= nelem4) return;
    float4 v = *(const float4*)(in + (size_t)i * 4);
    bf16* o = out + (size_t)i * 4;
    o[0] = __float2bfloat16(v.x); o[1] = __float2bfloat16(v.y);
    o[2] = __float2bfloat16(v.z); o[3] = __float2bfloat16(v.w);
}

// ---------------- RMSNorm: one block per token row, D=768=3*256 ----------------
template <typename TO>
__global__ void rmsnorm_kernel(const float* __restrict__ x, const float* __restrict__ w,
                               TO* __restrict__ out) {
    int row = blockIdx.x;
    const float* xr = x + (size_t)row * D_;
    TO* outr = out + (size_t)row * D_;
    int tid = threadIdx.x;
    float v[3];
    float s = 0.f;
#pragma unroll
    for (int i = 0; i < 3; i++) { v[i] = xr[tid + i * 256]; s += v[i] * v[i]; }
#pragma unroll
    for (int o = 16; o; o >>= 1) s += __shfl_xor_sync(~0u, s, o);
    __shared__ float red[8];
    __shared__ float total;
    if ((tid & 31) == 0) red[tid >> 5] = s;
    __syncthreads();
    if (tid < 8) {
        float t = red[tid];
#pragma unroll
        for (int o = 4; o; o >>= 1) t += __shfl_xor_sync(0xffu, t, o);
        if (tid == 0) total = t;
    }
    __syncthreads();
    float scale = rsqrtf(total * (1.f / D_) + EPSN);
#pragma unroll
    for (int i = 0; i < 3; i++) outr[tid + i * 256] = (TO)(v[i] * scale * w[tid + i * 256]);
}

// ---------------- bf16 tensor-core GEMM: C[M,N] = A[M,K] * B[N,K]^T ------------
// 128x128x32 block tile, 8 warps (4x2), warp tile 32x64, mma.m16n8k16.bf16,
// ldmatrix.x4 fragment loads, cp.async.cg 2-stage double buffer.
// pitch-40 (80B rows, 16B-aligned, conflict-free for ldmatrix).
// Requires M%128==0, N%128==0, K%32==0.
// EPI: 0 = store fp32, 2 = C += acc (residual add)
#define PITCH 40
#define STG_E (128 * PITCH)
template <int EPI>
__global__ void __launch_bounds__(256) mma_bf(
    const bf16* __restrict__ A, const bf16* __restrict__ Bw, float* __restrict__ C,
    int M, int N, int Kd, int lda, int ldb, int ldc) {
    __shared__ bf16 As[2][STG_E];
    __shared__ bf16 Bs[2][STG_E];
    int tid = threadIdx.x;
    int lane = tid & 31, warp = tid >> 5;
    int bm = blockIdx.y * 128, bn = blockIdx.x * 128;
    int wm = (warp & 3) * 32, wn = (warp >> 2) * 64;
    int g = lane >> 2, t4 = lane & 3;

    // ldmatrix source addresses (per-lane, per stage)
    int l15 = lane & 15;            // row within 16-row panel
    int lkh = (lane >> 4) << 3;     // k-half select: 0 / 8 elements
    uint32_t aoff[2][2], boff[2][4];
#pragma unroll
    for (int s = 0; s < 2; s++) {
#pragma unroll
        for (int mt = 0; mt < 2; mt++)
            aoff[s][mt] = s2u(&As[s][(wm + mt * 16 + l15) * PITCH + lkh]);
#pragma unroll
        for (int p = 0; p < 4; p++)
            boff[s][p] = s2u(&Bs[s][(wn + p * 16 + lkh + (lane & 7)) * PITCH + (lane & 8)]);
    }

    float acc[2][8][4];
#pragma unroll
    for (int i = 0; i < 2; i++)
#pragma unroll
        for (int j = 0; j < 8; j++)
#pragma unroll
            for (int q = 0; q < 4; q++) acc[i][j][q] = 0.f;

    const bf16* Ag = A + (size_t)bm * lda;
    const bf16* Bg = Bw + (size_t)bn * ldb;
    int NT = Kd >> 5;  // K/32 tiles

    // loader mapping: 512 16B-chunks per tile per operand; 256 threads -> 2 each
    int lr0 = tid >> 2, lkc = (tid & 3) << 3;   // chunk tid
    int lr1 = lr0 + 64;                          // chunk tid+256

    // ---- issue tile 0 into stage 0 ----
    {
        asm volatile("cp.async.cg.shared.global [%0], [%1], 16;\n"
                     :: "r"(s2u(&As[0][lr0 * PITCH + lkc])),
                        "l"(Ag + (size_t)lr0 * lda + lkc));
        asm volatile("cp.async.cg.shared.global [%0], [%1], 16;\n"
                     :: "r"(s2u(&As[0][lr1 * PITCH + lkc])),
                        "l"(Ag + (size_t)lr1 * lda + lkc));
        asm volatile("cp.async.cg.shared.global [%0], [%1], 16;\n"
                     :: "r"(s2u(&Bs[0][lr0 * PITCH + lkc])),
                        "l"(Bg + (size_t)lr0 * ldb + lkc));
        asm volatile("cp.async.cg.shared.global [%0], [%1], 16;\n"
                     :: "r"(s2u(&Bs[0][lr1 * PITCH + lkc])),
                        "l"(Bg + (size_t)lr1 * ldb + lkc));
        asm volatile("cp.async.commit_group;\n" ::);
    }

    for (int kt = 0; kt < NT; kt++) {
        int s = kt & 1;
        if (kt + 1 < NT) {
            int ns = s ^ 1;
            int kb = (kt + 1) << 5;
            asm volatile("cp.async.cg.shared.global [%0], [%1], 16;\n"
                         :: "r"(s2u(&As[ns][lr0 * PITCH + lkc])),
                            "l"(Ag + (size_t)lr0 * lda + kb + lkc));
            asm volatile("cp.async.cg.shared.global [%0], [%1], 16;\n"
                         :: "r"(s2u(&As[ns][lr1 * PITCH + lkc])),
                            "l"(Ag + (size_t)lr1 * lda + kb + lkc));
            asm volatile("cp.async.cg.shared.global [%0], [%1], 16;\n"
                         :: "r"(s2u(&Bs[ns][lr0 * PITCH + lkc])),
                            "l"(Bg + (size_t)lr0 * ldb + kb + lkc));
            asm volatile("cp.async.cg.shared.global [%0], [%1], 16;\n"
                         :: "r"(s2u(&Bs[ns][lr1 * PITCH + lkc])),
                            "l"(Bg + (size_t)lr1 * ldb + kb + lkc));
            asm volatile("cp.async.commit_group;\n" ::);
            asm volatile("cp.async.wait_group 1;\n" ::);
        } else {
            asm volatile("cp.async.wait_group 0;\n" ::);
        }
        __syncthreads();
#pragma unroll
        for (int kk = 0; kk < 32; kk += 16) {
            uint32_t af[2][4];
#pragma unroll
            for (int mt = 0; mt < 2; mt++) {
                asm volatile(
                    "ldmatrix.sync.aligned.m8n8.x4.shared.b16 {%0,%1,%2,%3}, [%4];"
                    : "=r"(af[mt][0]), "=r"(af[mt][1]), "=r"(af[mt][2]), "=r"(af[mt][3])
                    : "r"(aoff[s][mt] + kk * 2));
            }
            uint32_t bfr[8][2];
#pragma unroll
            for (int p = 0; p < 4; p++) {
                asm volatile(
                    "ldmatrix.sync.aligned.m8n8.x4.shared.b16 {%0,%1,%2,%3}, [%4];"
                    : "=r"(bfr[2 * p][0]), "=r"(bfr[2 * p][1]),
                      "=r"(bfr[2 * p + 1][0]), "=r"(bfr[2 * p + 1][1])
                    : "r"(boff[s][p] + kk * 2));
            }
#pragma unroll
            for (int mt = 0; mt < 2; mt++)
#pragma unroll
                for (int nt = 0; nt < 8; nt++) {
                    asm volatile(
                        "mma.sync.aligned.m16n8k16.row.col.f32.bf16.bf16.f32 "
                        "{%0,%1,%2,%3},{%4,%5,%6,%7},{%8,%9},{%0,%1,%2,%3};"
                        : "+f"(acc[mt][nt][0]), "+f"(acc[mt][nt][1]),
                          "+f"(acc[mt][nt][2]), "+f"(acc[mt][nt][3])
                        : "r"(af[mt][0]), "r"(af[mt][1]), "r"(af[mt][2]), "r"(af[mt][3]),
                          "r"(bfr[nt][0]), "r"(bfr[nt][1]));
                }
        }
        __syncthreads();
    }

    // epilogue: thread owns (rows g/g+8, cols 2*t4..2*t4+1) per 16x8 tile
#pragma unroll
    for (int mt = 0; mt < 2; mt++) {
        int rr = bm + wm + mt * 16 + g;
#pragma unroll
        for (int nt = 0; nt < 8; nt++) {
            int col = bn + wn + nt * 8 + t4 * 2;
            float v0 = acc[mt][nt][0], v1 = acc[mt][nt][1];
            float v2 = acc[mt][nt][2], v3 = acc[mt][nt][3];
            float* p0 = &C[(size_t)rr * ldc + col];
            float* p1 = &C[(size_t)(rr + 8) * ldc + col];
            if (EPI == 2) {
                float2 o0 = *(float2*)p0, o1 = *(float2*)p1;
                v0 += o0.x; v1 += o0.y; v2 += o1.x; v3 += o1.y;
            }
            *(float2*)p0 = make_float2(v0, v1);
            *(float2*)p1 = make_float2(v2, v3);
        }
    }
}

// ---------------- TF32 GEMM (kept for dt_proj, K=48) ---------------------------
__device__ __forceinline__ uint32_t f2tf(float f) {
    uint32_t u;
    asm("cvt.rna.tf32.f32 %0, %1;" : "=r"(u) : "f"(f));
    return u;
}
__device__ __forceinline__ float softplus_f(float v) {
    return v > 20.f ? v : __logf(1.f + __expf(v));
}

__global__ void __launch_bounds__(256) mma_nt_sp(
    const float* __restrict__ A, const float* __restrict__ Bw, float* __restrict__ C,
    int M, int N, int Kd, int lda, int ldb, int ldc, const float* __restrict__ bias) {
    __shared__ uint32_t As[128 * 20];
    __shared__ uint32_t Bs[128 * 20];
    int tid = threadIdx.x;
    int bm = blockIdx.y * 128, bn = blockIdx.x * 128;
    int ldr = tid >> 1;
    int cc = (tid & 1) << 3;
    const float* Ap = A + (size_t)(bm + ldr) * lda + cc;
    const float* Bp = Bw + (size_t)(bn + ldr) * ldb + cc;
    int lane = tid & 31;
    int g = lane >> 2, t4 = lane & 3;
    int warp = tid >> 5;
    int wm = (warp & 3) * 32, wn = (warp >> 2) * 64;
    float acc[2][8][4];
#pragma unroll
    for (int i = 0; i < 2; i++)
#pragma unroll
        for (int j = 0; j < 8; j++)
#pragma unroll
            for (int q = 0; q < 4; q++) acc[i][j][q] = 0.f;
    float4 pa0 = *(const float4*)(Ap);
    float4 pa1 = *(const float4*)(Ap + 4);
    float4 pb0 = *(const float4*)(Bp);
    float4 pb1 = *(const float4*)(Bp + 4);
    for (int k0 = 0; k0 < Kd; k0 += 16) {
        uint32_t* da = &As[ldr * 20 + cc];
        da[0] = f2tf(pa0.x); da[1] = f2tf(pa0.y); da[2] = f2tf(pa0.z); da[3] = f2tf(pa0.w);
        da[4] = f2tf(pa1.x); da[5] = f2tf(pa1.y); da[6] = f2tf(pa1.z); da[7] = f2tf(pa1.w);
        uint32_t* db = &Bs[ldr * 20 + cc];
        db[0] = f2tf(pb0.x); db[1] = f2tf(pb0.y); db[2] = f2tf(pb0.z); db[3] = f2tf(pb0.w);
        db[4] = f2tf(pb1.x); db[5] = f2tf(pb1.y); db[6] = f2tf(pb1.z); db[7] = f2tf(pb1.w);
        __syncthreads();
        if (k0 + 16 < Kd) {
            pa0 = *(const float4*)(Ap + k0 + 16);
            pa1 = *(const float4*)(Ap + k0 + 20);
            pb0 = *(const float4*)(Bp + k0 + 16);
            pb1 = *(const float4*)(Bp + k0 + 20);
        }
#pragma unroll
        for (int kk = 0; kk < 16; kk += 8) {
            uint32_t af[2][4];
#pragma unroll
            for (int mt = 0; mt < 2; mt++) {
                int r = wm + mt * 16;
                af[mt][0] = As[(r + g) * 20 + kk + t4];
                af[mt][1] = As[(r + g + 8) * 20 + kk + t4];
                af[mt][2] = As[(r + g) * 20 + kk + t4 + 4];
                af[mt][3] = As[(r + g + 8) * 20 + kk + t4 + 4];
            }
            uint32_t bfr[8][2];
#pragma unroll
            for (int nt = 0; nt < 8; nt++) {
                int ccol = wn + nt * 8;
                bfr[nt][0] = Bs[(ccol + g) * 20 + kk + t4];
                bfr[nt][1] = Bs[(ccol + g) * 20 + kk + t4 + 4];
            }
#pragma unroll
            for (int mt = 0; mt < 2; mt++)
#pragma unroll
                for (int nt = 0; nt < 8; nt++) {
                    asm volatile(
                        "mma.sync.aligned.m16n8k8.row.col.f32.tf32.tf32.f32 "
                        "{%0,%1,%2,%3},{%4,%5,%6,%7},{%8,%9},{%0,%1,%2,%3};"
                        : "+f"(acc[mt][nt][0]), "+f"(acc[mt][nt][1]),
                          "+f"(acc[mt][nt][2]), "+f"(acc[mt][nt][3])
                        : "r"(af[mt][0]), "r"(af[mt][1]), "r"(af[mt][2]), "r"(af[mt][3]),
                          "r"(bfr[nt][0]), "r"(bfr[nt][1]));
                }
        }
        __syncthreads();
    }
#pragma unroll
    for (int mt = 0; mt < 2; mt++) {
        int r0 = bm + wm + mt * 16 + g;
#pragma unroll
        for (int nt = 0; nt < 8; nt++) {
            int col = bn + wn + nt * 8 + t4 * 2;
            float b0v = bias[col], b1v = bias[col + 1];
            float v0 = softplus_f(acc[mt][nt][0] + b0v);
            float v1 = softplus_f(acc[mt][nt][1] + b1v);
            float v2 = softplus_f(acc[mt][nt][2] + b0v);
            float v3 = softplus_f(acc[mt][nt][3] + b1v);
            *(float2*)&C[(size_t)r0 * ldc + col] = make_float2(v0, v1);
            *(float2*)&C[(size_t)(r0 + 8) * ldc + col] = make_float2(v2, v3);
        }
    }
}

// ---------------- Causal depthwise conv (Kconv=4) + SiLU ----------------
__global__ void conv_silu_kernel(const float* __restrict__ proj, const float* __restrict__ cw,
                                 const float* __restrict__ cb, float* __restrict__ u) {
    int idx = blockIdx.x * blockDim.x + threadIdx.x;
    if (idx >= T_ * E_) return;
    int e = idx % E_;
    int t = idx / E_;
    int l = t % L_;
    float4 w = *(const float4*)(cw + e * 4);  // w.x oldest (l-3) ... w.w current (l)
    const float* p = proj + (size_t)t * 2 * E_ + e;
    float acc = cb[e];
    if (l >= 3) acc += w.x * p[-(3 * 2 * E_)];
    if (l >= 2) acc += w.y * p[-(2 * 2 * E_)];
    if (l >= 1) acc += w.z * p[-(1 * 2 * E_)];
    acc += w.w * p[0];
    u[idx] = acc / (1.f + __expf(-acc));  // silu
}

// ---------------- x_proj split-K: ssm[T,80] += u[T,Kslice] @ W[80,Kslice]^T ----
#define KSPLIT 8
#define KSL    (E_/KSPLIT)  // 192
__global__ void __launch_bounds__(256) xproj_kernel(const float* __restrict__ U,
                                                    const float* __restrict__ W,
                                                    float* __restrict__ out) {
    __shared__ float As[16][68];
    __shared__ float Bs[16][84];
    int tid = threadIdx.x;
    int t0 = blockIdx.x * 64;
    int kbase = blockIdx.y * KSL;
    int tx = tid & 15, ty = tid >> 4;  // cols tx*5.., rows ty*4..
    int ar = tid >> 2, ac = (tid & 3) << 2;
    float acc[4][5] = {};
    for (int k0 = kbase; k0 < kbase + KSL; k0 += 16) {
        float4 av = *(const float4*)(U + (size_t)(t0 + ar) * E_ + k0 + ac);
        As[ac + 0][ar] = av.x; As[ac + 1][ar] = av.y;
        As[ac + 2][ar] = av.z; As[ac + 3][ar] = av.w;
#pragma unroll
        for (int i = 0; i < 2; i++) {
            int li = tid + i * 256;
            if (li < 320) {
                int br = li >> 2, bc = (li & 3) << 2;
                float4 bv = *(const float4*)(W + (size_t)br * E_ + k0 + bc);
                Bs[bc + 0][br] = bv.x; Bs[bc + 1][br] = bv.y;
                Bs[bc + 2][br] = bv.z; Bs[bc + 3][br] = bv.w;
            }
        }
        __syncthreads();
#pragma unroll
        for (int k = 0; k < 16; k++) {
            float4 a = *(const float4*)&As[k][ty * 4];
            float ar4[4] = {a.x, a.y, a.z, a.w};
#pragma unroll
            for (int j = 0; j < 5; j++) {
                float bvv = Bs[k][tx * 5 + j];
#pragma unroll
                for (int i = 0; i < 4; i++) acc[i][j] += ar4[i] * bvv;
            }
        }
        __syncthreads();
    }
#pragma unroll
    for (int i = 0; i < 4; i++)
#pragma unroll
        for (int j = 0; j < 5; j++)
            atomicAdd(&out[(size_t)(t0 + ty * 4 + i) * G_ + tx * 5 + j], acc[i][j]);
}

// ---------------- Chunked selective scan, pass 1: per-chunk (P, S) ------------
// idx bits: n = idx&15, c = (idx>>4)&15, pe = idx>>8 (pe = b*E+e)
__global__ void __launch_bounds__(256) scan_p1(
    const float* __restrict__ dt, const float* __restrict__ u,
    const float* __restrict__ ssm, const float* __restrict__ A_log) {
    int idx = blockIdx.x * 256 + threadIdx.x;
    int n = idx & (N_ - 1);
    int c = (idx >> 4) & (NCH - 1);
    int pe = idx >> 8;
    int b = pe / E_, e = pe - b * E_;
    float Av = -__expf(A_log[e * N_ + n]);
    int t0 = c * CHL;
    const float* dtp = dt + ((size_t)b * L_ + t0) * E_ + e;
    const float* up  = u  + ((size_t)b * L_ + t0) * E_ + e;
    const float* sp  = ssm + ((size_t)b * L_ + t0) * G_;
    float P = 1.f, s = 0.f;
    for (int i = 0; i < CHL; i++) {
        float dtv = dtp[(size_t)i * E_];
        float uv  = up[(size_t)i * E_];
        float Bv  = sp[(size_t)i * G_ + DTR_ + n];
        float dA = __expf(dtv * Av);
        P *= dA;
        s = s * dA + (dtv * Bv) * uv;
    }
    size_t o = (size_t)c * BEN + (size_t)pe * N_ + n;
    g_cP[o] = P;
    g_cS[o] = s;
}

// ---------------- pass 2: serial combine over chunks (tiny) -------------------
__global__ void __launch_bounds__(256) scan_p2() {
    int i = blockIdx.x * 256 + threadIdx.x;   // 0..BEN-1
    float s = 0.f;
#pragma unroll
    for (int c = 0; c < NCH; c++) {
        size_t o = (size_t)c * BEN + i;
        g_cI[o] = s;
        s = g_cP[o] * s + g_cS[o];
    }
}

// ---------------- pass 3: re-scan chunk with correct init, emit y (bf16) ------
__global__ void __launch_bounds__(256) scan_p3(
    const float* __restrict__ dt, const float* __restrict__ u,
    const float* __restrict__ ssm, const float* __restrict__ proj,
    const float* __restrict__ A_log, const float* __restrict__ Dsk,
    bf16* __restrict__ y) {
    int idx = blockIdx.x * 256 + threadIdx.x;
    int n = idx & (N_ - 1);
    int c = (idx >> 4) & (NCH - 1);
    int pe = idx >> 8;
    int b = pe / E_, e = pe - b * E_;
    float Av = -__expf(A_log[e * N_ + n]);
    float Dv = Dsk[e];
    int t0 = c * CHL;
    const float* dtp = dt + ((size_t)b * L_ + t0) * E_ + e;
    const float* up  = u  + ((size_t)b * L_ + t0) * E_ + e;
    const float* sp  = ssm + ((size_t)b * L_ + t0) * G_;
    const float* gp  = proj + ((size_t)b * L_ + t0) * 2 * E_ + E_ + e;
    bf16* yp = y + ((size_t)b * L_ + t0) * E_ + e;
    float s = g_cI[(size_t)c * BEN + (size_t)pe * N_ + n];
    for (int i = 0; i < CHL; i++) {
        float dtv = dtp[(size_t)i * E_];
        float uv  = up[(size_t)i * E_];
        float Bv  = sp[(size_t)i * G_ + DTR_ + n];
        float Cv  = sp[(size_t)i * G_ + DTR_ + N_ + n];
        float dA = __expf(dtv * Av);
        s = s * dA + (dtv * Bv) * uv;
        float r = s * Cv;
        r += __shfl_xor_sync(~0u, r, 8);
        r += __shfl_xor_sync(~0u, r, 4);
        r += __shfl_xor_sync(~0u, r, 2);
        r += __shfl_xor_sync(~0u, r, 1);
        if (n == 0) {
            float gv = gp[(size_t)i * 2 * E_];
            float sig = gv / (1.f + __expf(-gv));
            yp[(size_t)i * E_] = __float2bfloat16((r + uv * Dv) * sig);
        }
    }
}

// ---------------- launch ----------------
extern "C" void kernel_launch(void* const* d_in, const int* in_sizes, int n_in,
                              void* d_out, int out_size) {
    const float* x            = (const float*)d_in[0];
    const float* norm_w       = (const float*)d_in[1];
    const float* in_proj_w    = (const float*)d_in[2];
    const float* conv_w       = (const float*)d_in[3];
    const float* conv_b       = (const float*)d_in[4];
    const float* x_proj_w     = (const float*)d_in[5];
    const float* dt_proj_w    = (const float*)d_in[6];
    const float* dt_proj_b    = (const float*)d_in[7];
    const float* A_log        = (const float*)d_in[8];
    const float* D_skip       = (const float*)d_in[9];
    const float* out_proj_w   = (const float*)d_in[10];
    const float* final_norm_w = (const float*)d_in[11];

    float *h, *proj, *u, *ssm, *dt;
    bf16 *hn, *y, *win, *wout;
    cudaGetSymbolAddress((void**)&h, g_h);
    cudaGetSymbolAddress((void**)&hn, g_hn);
    cudaGetSymbolAddress((void**)&proj, g_proj);
    cudaGetSymbolAddress((void**)&u, g_u);
    cudaGetSymbolAddress((void**)&ssm, g_ssm);
    cudaGetSymbolAddress((void**)&dt, g_dt);
    cudaGetSymbolAddress((void**)&y, g_y);
    cudaGetSymbolAddress((void**)&win, g_win_bf);
    cudaGetSymbolAddress((void**)&wout, g_wout_bf);

    cudaMemcpyAsync(h, x, sizeof(float) * (size_t)T_ * D_, cudaMemcpyDeviceToDevice, 0);

    // one-time per-launch weight conversion to bf16
    {
        int n4 = NL_ * 2 * E_ * D_ / 4;
        f2bf_kernel<<<(n4 + 255) / 256, 256>>>(in_proj_w, win, n4);
        n4 = NL_ * D_ * E_ / 4;
        f2bf_kernel<<<(n4 + 255) / 256, 256>>>(out_proj_w, wout, n4);
    }

    for (int l = 0; l < NL_; l++) {
        rmsnorm_kernel<bf16><<<T_, 256>>>(h, norm_w + (size_t)l * D_, hn);

        // in_proj: (T,768) @ (3072,768)^T -> (T,3072)   [bf16 tensor cores]
        mma_bf<0><<<dim3(2 * E_ / 128, T_ / 128), 256>>>(
            hn, win + (size_t)l * 2 * E_ * D_, proj,
            T_, 2 * E_, D_, D_, D_, 2 * E_);

        conv_silu_kernel<<<(T_ * E_ + 255) / 256, 256>>>(
            proj, conv_w + (size_t)l * E_ * KC, conv_b + (size_t)l * E_, u);

        // x_proj: (T,1536) @ (80,1536)^T -> (T,80)  [split-K + atomics]
        cudaMemsetAsync(ssm, 0, sizeof(float) * (size_t)T_ * G_, 0);
        xproj_kernel<<<dim3(T_ / 64, KSPLIT), 256>>>(
            u, x_proj_w + (size_t)l * G_ * E_, ssm);

        // dt_proj + softplus: (T,48) @ (1536,48)^T -> (T,1536)  [tf32]
        mma_nt_sp<<<dim3(E_ / 128, T_ / 128), 256>>>(
            ssm, dt_proj_w + (size_t)l * E_ * DTR_, dt,
            T_, E_, DTR_, G_, DTR_, E_, dt_proj_b + (size_t)l * E_);

        // chunked selective scan
        scan_p1<<<(NCH * BEN) / 256, 256>>>(dt, u, ssm, A_log + (size_t)l * E_ * N_);
        scan_p2<<<BEN / 256, 256>>>();
        scan_p3<<<(NCH * BEN) / 256, 256>>>(dt, u, ssm, proj,
                                            A_log + (size_t)l * E_ * N_,
                                            D_skip + (size_t)l * E_, y);

        // out_proj + residual add: h += (T,1536) @ (768,1536)^T  [bf16]
        mma_bf<2><<<dim3(D_ / 128, T_ / 128), 256>>>(
            y, wout + (size_t)l * D_ * E_, h,
            T_, D_, E_, E_, E_, D_);
    }

    rmsnorm_kernel<float><<<T_, 256>>>(h, final_norm_w, (float*)d_out);
}

// round 10
// speedup vs baseline: 1.1673x; 1.1673x over previous
#include <cuda_runtime.h>
#include <cuda_bf16.h>
#include <cstdint>
#include <cstdio>

// Mamba (8 layers) forward: B=2, L=2048, D=768, E=1536, N=16, Kconv=4, DTR=48
#define B_   2
#define L_   2048
#define D_   768
#define E_   1536
#define N_   16
#define KC   4
#define DTR_ 48
#define NL_  8
#define T_   (B_*L_)        // 4096 tokens
#define G_   (DTR_ + 2*N_)  // 80
#define EPSN 1e-5f
#define NCH  16             // scan chunks
#define CHL  (L_/NCH)       // 128 chunk length
#define BEN  (B_*E_*N_)     // 49152

typedef __nv_bfloat16 bf16;

// ---------------- scratch (static device globals; no allocation) ----------------
__device__ float g_h[(size_t)T_ * D_];          // residual stream (fp32)
__device__ bf16  g_hn[(size_t)T_ * D_];         // rmsnormed (bf16 for GEMM A)
__device__ float g_proj[(size_t)T_ * 2 * E_];   // in_proj out (u_pre | gate)
__device__ bf16  g_u[(size_t)T_ * E_];          // conv+silu out (bf16)
__device__ float g_ssm[(size_t)T_ * G_];        // x_proj out (dt_r | B | C)
__device__ bf16  g_dt[(size_t)T_ * E_];         // softplus dt (bf16)
__device__ bf16  g_y[(size_t)T_ * E_];          // scan out * silu(gate) (bf16)
__device__ float g_cP[(size_t)NCH * BEN];       // per-chunk decay product
__device__ float g_cS[(size_t)NCH * BEN];       // per-chunk local state
__device__ float g_cI[(size_t)NCH * BEN];       // per-chunk initial state
__device__ bf16  g_win_bf[(size_t)NL_ * 2 * E_ * D_];   // bf16 in_proj weights
__device__ bf16  g_wout_bf[(size_t)NL_ * D_ * E_];      // bf16 out_proj weights

__device__ __forceinline__ uint32_t s2u(const void* p) {
    return (uint32_t)__cvta_generic_to_shared(p);
}

// ---------------- fp32 -> bf16 weight conversion (grid-stride, x4) -------------
__global__ void f2bf_kernel(const float* __restrict__ in, bf16* __restrict__ out,
                            int nelem4) {
    int i = blockIdx.x * blockDim.x + threadIdx.x;
    if (i >= nelem4) return;
    float4 v = *(const float4*)(in + (size_t)i * 4);
    bf16* o = out + (size_t)i * 4;
    o[0] = __float2bfloat16(v.x); o[1] = __float2bfloat16(v.y);
    o[2] = __float2bfloat16(v.z); o[3] = __float2bfloat16(v.w);
}

// ---------------- RMSNorm: one block per token row, D=768=3*256 ----------------
template <typename TO>
__global__ void rmsnorm_kernel(const float* __restrict__ x, const float* __restrict__ w,
                               TO* __restrict__ out) {
    int row = blockIdx.x;
    const float* xr = x + (size_t)row * D_;
    TO* outr = out + (size_t)row * D_;
    int tid = threadIdx.x;
    float v[3];
    float s = 0.f;
#pragma unroll
    for (int i = 0; i < 3; i++) { v[i] = xr[tid + i * 256]; s += v[i] * v[i]; }
#pragma unroll
    for (int o = 16; o; o >>= 1) s += __shfl_xor_sync(~0u, s, o);
    __shared__ float red[8];
    __shared__ float total;
    if ((tid & 31) == 0) red[tid >> 5] = s;
    __syncthreads();
    if (tid < 8) {
        float t = red[tid];
#pragma unroll
        for (int o = 4; o; o >>= 1) t += __shfl_xor_sync(0xffu, t, o);
        if (tid == 0) total = t;
    }
    __syncthreads();
    float scale = rsqrtf(total * (1.f / D_) + EPSN);
#pragma unroll
    for (int i = 0; i < 3; i++) outr[tid + i * 256] = (TO)(v[i] * scale * w[tid + i * 256]);
}

// ---------------- bf16 tensor-core GEMM: C[M,N] = A[M,K] * B[N,K]^T ------------
// 128x128x32 block tile, 8 warps (4x2), warp tile 32x64, mma.m16n8k16.bf16,
// ldmatrix.x4 fragment loads (pitch-40: 80B rows, 16B-aligned, conflict-free).
// EPI: 0 = store fp32, 2 = C += acc (residual add)   [exact R7 version]
#define PITCH 40
template <int EPI>
__global__ void __launch_bounds__(256) mma_bf(
    const bf16* __restrict__ A, const bf16* __restrict__ Bw, float* __restrict__ C,
    int M, int N, int Kd, int lda, int ldb, int ldc) {
    __shared__ bf16 As[128 * PITCH];
    __shared__ bf16 Bs[128 * PITCH];
    int tid = threadIdx.x;
    int bm = blockIdx.y * 128, bn = blockIdx.x * 128;

    // loader: 512 chunks of 8 bf16 per tile; thread handles chunks tid, tid+256
    int r0 = tid >> 2, kc = (tid & 3) << 3;
    int r1 = r0 + 64;
    const bf16* Ap0 = A + (size_t)(bm + r0) * lda + kc;
    const bf16* Ap1 = A + (size_t)(bm + r1) * lda + kc;
    const bf16* Bp0 = Bw + (size_t)(bn + r0) * ldb + kc;
    const bf16* Bp1 = Bw + (size_t)(bn + r1) * ldb + kc;

    int lane = tid & 31;
    int g = lane >> 2, t4 = lane & 3;
    int warp = tid >> 5;
    int wm = (warp & 3) * 32, wn = (warp >> 2) * 64;

    // ldmatrix source addresses (per-lane row pointers)
    int l15 = lane & 15;            // row within 16-row panel
    int lkh = (lane >> 4) << 3;     // k-half: 0 / 8 elements
    uint32_t aoff[2], boff[4];
#pragma unroll
    for (int mt = 0; mt < 2; mt++)
        aoff[mt] = s2u(&As[(wm + mt * 16 + l15) * PITCH + lkh]);
#pragma unroll
    for (int p = 0; p < 4; p++)
        boff[p] = s2u(&Bs[(wn + p * 16 + lkh + (lane & 7)) * PITCH + (lane & 8)]);

    float acc[2][8][4];
#pragma unroll
    for (int i = 0; i < 2; i++)
#pragma unroll
        for (int j = 0; j < 8; j++)
#pragma unroll
            for (int q = 0; q < 4; q++) acc[i][j][q] = 0.f;

    // prefetch first K-tile
    uint4 qa0 = *(const uint4*)Ap0;
    uint4 qa1 = *(const uint4*)Ap1;
    uint4 qb0 = *(const uint4*)Bp0;
    uint4 qb1 = *(const uint4*)Bp1;

    for (int k0 = 0; k0 < Kd; k0 += 32) {
        *(uint4*)&As[r0 * PITCH + kc] = qa0;
        *(uint4*)&As[r1 * PITCH + kc] = qa1;
        *(uint4*)&Bs[r0 * PITCH + kc] = qb0;
        *(uint4*)&Bs[r1 * PITCH + kc] = qb1;
        __syncthreads();
        if (k0 + 32 < Kd) {
            qa0 = *(const uint4*)(Ap0 + k0 + 32);
            qa1 = *(const uint4*)(Ap1 + k0 + 32);
            qb0 = *(const uint4*)(Bp0 + k0 + 32);
            qb1 = *(const uint4*)(Bp1 + k0 + 32);
        }
#pragma unroll
        for (int kk = 0; kk < 32; kk += 16) {
            uint32_t af[2][4];
#pragma unroll
            for (int mt = 0; mt < 2; mt++) {
                asm volatile(
                    "ldmatrix.sync.aligned.m8n8.x4.shared.b16 {%0,%1,%2,%3}, [%4];"
                    : "=r"(af[mt][0]), "=r"(af[mt][1]), "=r"(af[mt][2]), "=r"(af[mt][3])
                    : "r"(aoff[mt] + kk * 2));
            }
            uint32_t bfr[8][2];
#pragma unroll
            for (int p = 0; p < 4; p++) {
                asm volatile(
                    "ldmatrix.sync.aligned.m8n8.x4.shared.b16 {%0,%1,%2,%3}, [%4];"
                    : "=r"(bfr[2 * p][0]), "=r"(bfr[2 * p][1]),
                      "=r"(bfr[2 * p + 1][0]), "=r"(bfr[2 * p + 1][1])
                    : "r"(boff[p] + kk * 2));
            }
#pragma unroll
            for (int mt = 0; mt < 2; mt++)
#pragma unroll
                for (int nt = 0; nt < 8; nt++) {
                    asm volatile(
                        "mma.sync.aligned.m16n8k16.row.col.f32.bf16.bf16.f32 "
                        "{%0,%1,%2,%3},{%4,%5,%6,%7},{%8,%9},{%0,%1,%2,%3};"
                        : "+f"(acc[mt][nt][0]), "+f"(acc[mt][nt][1]),
                          "+f"(acc[mt][nt][2]), "+f"(acc[mt][nt][3])
                        : "r"(af[mt][0]), "r"(af[mt][1]), "r"(af[mt][2]), "r"(af[mt][3]),
                          "r"(bfr[nt][0]), "r"(bfr[nt][1]));
                }
        }
        __syncthreads();
    }

    // epilogue: thread owns (rows g/g+8, cols 2*t4..2*t4+1) per 16x8 tile
#pragma unroll
    for (int mt = 0; mt < 2; mt++) {
        int rr = bm + wm + mt * 16 + g;
#pragma unroll
        for (int nt = 0; nt < 8; nt++) {
            int col = bn + wn + nt * 8 + t4 * 2;
            float v0 = acc[mt][nt][0], v1 = acc[mt][nt][1];
            float v2 = acc[mt][nt][2], v3 = acc[mt][nt][3];
            float* p0 = &C[(size_t)rr * ldc + col];
            float* p1 = &C[(size_t)(rr + 8) * ldc + col];
            if (EPI == 2) {
                float2 o0 = *(float2*)p0, o1 = *(float2*)p1;
                v0 += o0.x; v1 += o0.y; v2 += o1.x; v3 += o1.y;
            }
            *(float2*)p0 = make_float2(v0, v1);
            *(float2*)p1 = make_float2(v2, v3);
        }
    }
}

// ---------------- TF32 GEMM for dt_proj (K=48), bf16 output + softplus ---------
__device__ __forceinline__ uint32_t f2tf(float f) {
    uint32_t u;
    asm("cvt.rna.tf32.f32 %0, %1;" : "=r"(u) : "f"(f));
    return u;
}
__device__ __forceinline__ float softplus_f(float v) {
    return v > 20.f ? v : __logf(1.f + __expf(v));
}

__global__ void __launch_bounds__(256) mma_nt_sp(
    const float* __restrict__ A, const float* __restrict__ Bw, bf16* __restrict__ C,
    int M, int N, int Kd, int lda, int ldb, int ldc, const float* __restrict__ bias) {
    __shared__ uint32_t As[128 * 20];
    __shared__ uint32_t Bs[128 * 20];
    int tid = threadIdx.x;
    int bm = blockIdx.y * 128, bn = blockIdx.x * 128;
    int ldr = tid >> 1;
    int cc = (tid & 1) << 3;
    const float* Ap = A + (size_t)(bm + ldr) * lda + cc;
    const float* Bp = Bw + (size_t)(bn + ldr) * ldb + cc;
    int lane = tid & 31;
    int g = lane >> 2, t4 = lane & 3;
    int warp = tid >> 5;
    int wm = (warp & 3) * 32, wn = (warp >> 2) * 64;
    float acc[2][8][4];
#pragma unroll
    for (int i = 0; i < 2; i++)
#pragma unroll
        for (int j = 0; j < 8; j++)
#pragma unroll
            for (int q = 0; q < 4; q++) acc[i][j][q] = 0.f;
    float4 pa0 = *(const float4*)(Ap);
    float4 pa1 = *(const float4*)(Ap + 4);
    float4 pb0 = *(const float4*)(Bp);
    float4 pb1 = *(const float4*)(Bp + 4);
    for (int k0 = 0; k0 < Kd; k0 += 16) {
        uint32_t* da = &As[ldr * 20 + cc];
        da[0] = f2tf(pa0.x); da[1] = f2tf(pa0.y); da[2] = f2tf(pa0.z); da[3] = f2tf(pa0.w);
        da[4] = f2tf(pa1.x); da[5] = f2tf(pa1.y); da[6] = f2tf(pa1.z); da[7] = f2tf(pa1.w);
        uint32_t* db = &Bs[ldr * 20 + cc];
        db[0] = f2tf(pb0.x); db[1] = f2tf(pb0.y); db[2] = f2tf(pb0.z); db[3] = f2tf(pb0.w);
        db[4] = f2tf(pb1.x); db[5] = f2tf(pb1.y); db[6] = f2tf(pb1.z); db[7] = f2tf(pb1.w);
        __syncthreads();
        if (k0 + 16 < Kd) {
            pa0 = *(const float4*)(Ap + k0 + 16);
            pa1 = *(const float4*)(Ap + k0 + 20);
            pb0 = *(const float4*)(Bp + k0 + 16);
            pb1 = *(const float4*)(Bp + k0 + 20);
        }
#pragma unroll
        for (int kk = 0; kk < 16; kk += 8) {
            uint32_t af[2][4];
#pragma unroll
            for (int mt = 0; mt < 2; mt++) {
                int r = wm + mt * 16;
                af[mt][0] = As[(r + g) * 20 + kk + t4];
                af[mt][1] = As[(r + g + 8) * 20 + kk + t4];
                af[mt][2] = As[(r + g) * 20 + kk + t4 + 4];
                af[mt][3] = As[(r + g + 8) * 20 + kk + t4 + 4];
            }
            uint32_t bfr[8][2];
#pragma unroll
            for (int nt = 0; nt < 8; nt++) {
                int ccol = wn + nt * 8;
                bfr[nt][0] = Bs[(ccol + g) * 20 + kk + t4];
                bfr[nt][1] = Bs[(ccol + g) * 20 + kk + t4 + 4];
            }
#pragma unroll
            for (int mt = 0; mt < 2; mt++)
#pragma unroll
                for (int nt = 0; nt < 8; nt++) {
                    asm volatile(
                        "mma.sync.aligned.m16n8k8.row.col.f32.tf32.tf32.f32 "
                        "{%0,%1,%2,%3},{%4,%5,%6,%7},{%8,%9},{%0,%1,%2,%3};"
                        : "+f"(acc[mt][nt][0]), "+f"(acc[mt][nt][1]),
                          "+f"(acc[mt][nt][2]), "+f"(acc[mt][nt][3])
                        : "r"(af[mt][0]), "r"(af[mt][1]), "r"(af[mt][2]), "r"(af[mt][3]),
                          "r"(bfr[nt][0]), "r"(bfr[nt][1]));
                }
        }
        __syncthreads();
    }
#pragma unroll
    for (int mt = 0; mt < 2; mt++) {
        int r0 = bm + wm + mt * 16 + g;
#pragma unroll
        for (int nt = 0; nt < 8; nt++) {
            int col = bn + wn + nt * 8 + t4 * 2;
            float b0v = bias[col], b1v = bias[col + 1];
            float v0 = softplus_f(acc[mt][nt][0] + b0v);
            float v1 = softplus_f(acc[mt][nt][1] + b1v);
            float v2 = softplus_f(acc[mt][nt][2] + b0v);
            float v3 = softplus_f(acc[mt][nt][3] + b1v);
            *(__nv_bfloat162*)&C[(size_t)r0 * ldc + col] = __floats2bfloat162_rn(v0, v1);
            *(__nv_bfloat162*)&C[(size_t)(r0 + 8) * ldc + col] = __floats2bfloat162_rn(v2, v3);
        }
    }
}

// ---------------- Causal depthwise conv (Kconv=4) + SiLU -> bf16 ---------------
__global__ void conv_silu_kernel(const float* __restrict__ proj, const float* __restrict__ cw,
                                 const float* __restrict__ cb, bf16* __restrict__ u) {
    int idx = blockIdx.x * blockDim.x + threadIdx.x;
    if (idx >= T_ * E_) return;
    int e = idx % E_;
    int t = idx / E_;
    int l = t % L_;
    float4 w = *(const float4*)(cw + e * 4);  // w.x oldest (l-3) ... w.w current (l)
    const float* p = proj + (size_t)t * 2 * E_ + e;
    float acc = cb[e];
    if (l >= 3) acc += w.x * p[-(3 * 2 * E_)];
    if (l >= 2) acc += w.y * p[-(2 * 2 * E_)];
    if (l >= 1) acc += w.z * p[-(1 * 2 * E_)];
    acc += w.w * p[0];
    u[idx] = __float2bfloat16(acc / (1.f + __expf(-acc)));  // silu
}

// ---------------- x_proj split-K: ssm[T,80] += u[T,Kslice] @ W[80,Kslice]^T ----
// U is bf16 now (halved read traffic).
#define KSPLIT 8
#define KSL    (E_/KSPLIT)  // 192
__global__ void __launch_bounds__(256) xproj_kernel(const bf16* __restrict__ U,
                                                    const float* __restrict__ W,
                                                    float* __restrict__ out) {
    __shared__ float As[16][68];
    __shared__ float Bs[16][84];
    int tid = threadIdx.x;
    int t0 = blockIdx.x * 64;
    int kbase = blockIdx.y * KSL;
    int tx = tid & 15, ty = tid >> 4;  // cols tx*5.., rows ty*4..
    int ar = tid >> 2, ac = (tid & 3) << 2;
    float acc[4][5] = {};
    for (int k0 = kbase; k0 < kbase + KSL; k0 += 16) {
        uint2 raw = *(const uint2*)(U + (size_t)(t0 + ar) * E_ + k0 + ac);
        __nv_bfloat162 b01 = *reinterpret_cast<__nv_bfloat162*>(&raw.x);
        __nv_bfloat162 b23 = *reinterpret_cast<__nv_bfloat162*>(&raw.y);
        As[ac + 0][ar] = __low2float(b01); As[ac + 1][ar] = __high2float(b01);
        As[ac + 2][ar] = __low2float(b23); As[ac + 3][ar] = __high2float(b23);
#pragma unroll
        for (int i = 0; i < 2; i++) {
            int li = tid + i * 256;
            if (li < 320) {
                int br = li >> 2, bc = (li & 3) << 2;
                float4 bv = *(const float4*)(W + (size_t)br * E_ + k0 + bc);
                Bs[bc + 0][br] = bv.x; Bs[bc + 1][br] = bv.y;
                Bs[bc + 2][br] = bv.z; Bs[bc + 3][br] = bv.w;
            }
        }
        __syncthreads();
#pragma unroll
        for (int k = 0; k < 16; k++) {
            float4 a = *(const float4*)&As[k][ty * 4];
            float ar4[4] = {a.x, a.y, a.z, a.w};
#pragma unroll
            for (int j = 0; j < 5; j++) {
                float bvv = Bs[k][tx * 5 + j];
#pragma unroll
                for (int i = 0; i < 4; i++) acc[i][j] += ar4[i] * bvv;
            }
        }
        __syncthreads();
    }
#pragma unroll
    for (int i = 0; i < 4; i++)
#pragma unroll
        for (int j = 0; j < 5; j++)
            atomicAdd(&out[(size_t)(t0 + ty * 4 + i) * G_ + tx * 5 + j], acc[i][j]);
}

// ---------------- Chunked selective scan, pass 1: per-chunk (P, S) ------------
// idx bits: n = idx&15, c = (idx>>4)&15, pe = idx>>8 (pe = b*E+e)
__global__ void __launch_bounds__(256) scan_p1(
    const bf16* __restrict__ dt, const bf16* __restrict__ u,
    const float* __restrict__ ssm, const float* __restrict__ A_log) {
    int idx = blockIdx.x * 256 + threadIdx.x;
    int n = idx & (N_ - 1);
    int c = (idx >> 4) & (NCH - 1);
    int pe = idx >> 8;
    int b = pe / E_, e = pe - b * E_;
    float Av = -__expf(A_log[e * N_ + n]);
    int t0 = c * CHL;
    const bf16* dtp = dt + ((size_t)b * L_ + t0) * E_ + e;
    const bf16* up  = u  + ((size_t)b * L_ + t0) * E_ + e;
    const float* sp  = ssm + ((size_t)b * L_ + t0) * G_;
    float P = 1.f, s = 0.f;
    for (int i = 0; i < CHL; i++) {
        float dtv = __bfloat162float(dtp[(size_t)i * E_]);
        float uv  = __bfloat162float(up[(size_t)i * E_]);
        float Bv  = sp[(size_t)i * G_ + DTR_ + n];
        float dA = __expf(dtv * Av);
        P *= dA;
        s = s * dA + (dtv * Bv) * uv;
    }
    size_t o = (size_t)c * BEN + (size_t)pe * N_ + n;
    g_cP[o] = P;
    g_cS[o] = s;
}

// ---------------- pass 2: serial combine over chunks (tiny) -------------------
__global__ void __launch_bounds__(256) scan_p2() {
    int i = blockIdx.x * 256 + threadIdx.x;   // 0..BEN-1
    float s = 0.f;
#pragma unroll
    for (int c = 0; c < NCH; c++) {
        size_t o = (size_t)c * BEN + i;
        g_cI[o] = s;
        s = g_cP[o] * s + g_cS[o];
    }
}

// ---------------- pass 3: re-scan chunk with correct init, emit y (bf16) ------
__global__ void __launch_bounds__(256) scan_p3(
    const bf16* __restrict__ dt, const bf16* __restrict__ u,
    const float* __restrict__ ssm, const float* __restrict__ proj,
    const float* __restrict__ A_log, const float* __restrict__ Dsk,
    bf16* __restrict__ y) {
    int idx = blockIdx.x * 256 + threadIdx.x;
    int n = idx & (N_ - 1);
    int c = (idx >> 4) & (NCH - 1);
    int pe = idx >> 8;
    int b = pe / E_, e = pe - b * E_;
    float Av = -__expf(A_log[e * N_ + n]);
    float Dv = Dsk[e];
    int t0 = c * CHL;
    const bf16* dtp = dt + ((size_t)b * L_ + t0) * E_ + e;
    const bf16* up  = u  + ((size_t)b * L_ + t0) * E_ + e;
    const float* sp  = ssm + ((size_t)b * L_ + t0) * G_;
    const float* gp  = proj + ((size_t)b * L_ + t0) * 2 * E_ + E_ + e;
    bf16* yp = y + ((size_t)b * L_ + t0) * E_ + e;
    float s = g_cI[(size_t)c * BEN + (size_t)pe * N_ + n];
    for (int i = 0; i < CHL; i++) {
        float dtv = __bfloat162float(dtp[(size_t)i * E_]);
        float uv  = __bfloat162float(up[(size_t)i * E_]);
        float Bv  = sp[(size_t)i * G_ + DTR_ + n];
        float Cv  = sp[(size_t)i * G_ + DTR_ + N_ + n];
        float dA = __expf(dtv * Av);
        s = s * dA + (dtv * Bv) * uv;
        float r = s * Cv;
        r += __shfl_xor_sync(~0u, r, 8);
        r += __shfl_xor_sync(~0u, r, 4);
        r += __shfl_xor_sync(~0u, r, 2);
        r += __shfl_xor_sync(~0u, r, 1);
        if (n == 0) {
            float gv = gp[(size_t)i * 2 * E_];
            float sig = gv / (1.f + __expf(-gv));
            yp[(size_t)i * E_] = __float2bfloat16((r + uv * Dv) * sig);
        }
    }
}

// ---------------- launch ----------------
extern "C" void kernel_launch(void* const* d_in, const int* in_sizes, int n_in,
                              void* d_out, int out_size) {
    const float* x            = (const float*)d_in[0];
    const float* norm_w       = (const float*)d_in[1];
    const float* in_proj_w    = (const float*)d_in[2];
    const float* conv_w       = (const float*)d_in[3];
    const float* conv_b       = (const float*)d_in[4];
    const float* x_proj_w     = (const float*)d_in[5];
    const float* dt_proj_w    = (const float*)d_in[6];
    const float* dt_proj_b    = (const float*)d_in[7];
    const float* A_log        = (const float*)d_in[8];
    const float* D_skip       = (const float*)d_in[9];
    const float* out_proj_w   = (const float*)d_in[10];
    const float* final_norm_w = (const float*)d_in[11];

    float *h, *proj, *ssm;
    bf16 *hn, *u, *dt, *y, *win, *wout;
    cudaGetSymbolAddress((void**)&h, g_h);
    cudaGetSymbolAddress((void**)&hn, g_hn);
    cudaGetSymbolAddress((void**)&proj, g_proj);
    cudaGetSymbolAddress((void**)&u, g_u);
    cudaGetSymbolAddress((void**)&ssm, g_ssm);
    cudaGetSymbolAddress((void**)&dt, g_dt);
    cudaGetSymbolAddress((void**)&y, g_y);
    cudaGetSymbolAddress((void**)&win, g_win_bf);
    cudaGetSymbolAddress((void**)&wout, g_wout_bf);

    cudaMemcpyAsync(h, x, sizeof(float) * (size_t)T_ * D_, cudaMemcpyDeviceToDevice, 0);

    // one-time per-launch weight conversion to bf16
    {
        int n4 = NL_ * 2 * E_ * D_ / 4;
        f2bf_kernel<<<(n4 + 255) / 256, 256>>>(in_proj_w, win, n4);
        n4 = NL_ * D_ * E_ / 4;
        f2bf_kernel<<<(n4 + 255) / 256, 256>>>(out_proj_w, wout, n4);
    }

    for (int l = 0; l < NL_; l++) {
        rmsnorm_kernel<bf16><<<T_, 256>>>(h, norm_w + (size_t)l * D_, hn);

        // in_proj: (T,768) @ (3072,768)^T -> (T,3072)   [bf16 tensor cores]
        mma_bf<0><<<dim3(2 * E_ / 128, T_ / 128), 256>>>(
            hn, win + (size_t)l * 2 * E_ * D_, proj,
            T_, 2 * E_, D_, D_, D_, 2 * E_);

        conv_silu_kernel<<<(T_ * E_ + 255) / 256, 256>>>(
            proj, conv_w + (size_t)l * E_ * KC, conv_b + (size_t)l * E_, u);

        // x_proj: (T,1536) @ (80,1536)^T -> (T,80)  [split-K + atomics, bf16 in]
        cudaMemsetAsync(ssm, 0, sizeof(float) * (size_t)T_ * G_, 0);
        xproj_kernel<<<dim3(T_ / 64, KSPLIT), 256>>>(
            u, x_proj_w + (size_t)l * G_ * E_, ssm);

        // dt_proj + softplus: (T,48) @ (1536,48)^T -> (T,1536) bf16  [tf32]
        mma_nt_sp<<<dim3(E_ / 128, T_ / 128), 256>>>(
            ssm, dt_proj_w + (size_t)l * E_ * DTR_, dt,
            T_, E_, DTR_, G_, DTR_, E_, dt_proj_b + (size_t)l * E_);

        // chunked selective scan
        scan_p1<<<(NCH * BEN) / 256, 256>>>(dt, u, ssm, A_log + (size_t)l * E_ * N_);
        scan_p2<<<BEN / 256, 256>>>();
        scan_p3<<<(NCH * BEN) / 256, 256>>>(dt, u, ssm, proj,
                                            A_log + (size_t)l * E_ * N_,
                                            D_skip + (size_t)l * E_, y);

        // out_proj + residual add: h += (T,1536) @ (768,1536)^T  [bf16]
        mma_bf<2><<<dim3(D_ / 128, T_ / 128), 256>>>(
            y, wout + (size_t)l * D_ * E_, h,
            T_, D_, E_, E_, E_, D_);
    }

    rmsnorm_kernel<float><<<T_, 256>>>(h, final_norm_w, (float*)d_out);
}